// round 1
// baseline (speedup 1.0000x reference)
#include <cuda_runtime.h>

#define B   4
#define C   64
#define H   96
#define W   96
#define DD  8
#define NS  9      // 2S+1 spatial shifts per axis
#define NK  3      // 2D+1 depth shifts
#define NIDX 243
#define HW  (H*W)          // 9216
#define HWD (H*W*DD)       // 73728
#define CHWD ((size_t)C*HWD)

#define SMEM_F1 (64*32*10)     // [c][lx][z pad10]
#define SMEM_F2 (16*40*10)     // [cl][col][zpad10]
#define SMEM_BYTES ((SMEM_F1 + SMEM_F2)*4)

__device__ float g_m1[B*HW];
__device__ float g_m2[B*HW];

// ---------------------------------------------------------------------------
// Kernel 1: per-pixel clipped alpha sums (mask1 / mask2 bases)
// ---------------------------------------------------------------------------
__global__ void mask_sum_kernel(const float* __restrict__ a1,
                                const float* __restrict__ a2) {
    int n = blockIdx.x * blockDim.x + threadIdx.x;
    if (n >= B*HW) return;
    const float4* p1 = (const float4*)(a1 + (size_t)n * DD);
    const float4* p2 = (const float4*)(a2 + (size_t)n * DD);
    float4 u = p1[0], v = p1[1];
    float s1 = u.x+u.y+u.z+u.w + v.x+v.y+v.z+v.w;
    u = p2[0]; v = p2[1];
    float s2 = u.x+u.y+u.z+u.w + v.x+v.y+v.z+v.w;
    g_m1[n] = fminf(fmaxf(s1, 0.f), 1.f);
    g_m2[n] = fminf(fmaxf(s2, 0.f), 1.f);
}

// ---------------------------------------------------------------------------
// Kernel 2: cost_volume_mask (pure bandwidth). m2 padded with 1.0 everywhere.
// ---------------------------------------------------------------------------
__global__ void mask_out_kernel(float* __restrict__ om) {
    long n = (long)blockIdx.x * blockDim.x + threadIdx.x;
    if (n >= (long)B*NIDX*HW) return;
    int x   = (int)(n % W);
    int y   = (int)((n / W) % H);
    int idx = (int)((n / HW) % NIDX);
    int b   = (int)(n / ((long)HW * NIDX));
    int k = idx / 81;
    int r = idx - k*81;
    int i = r / 9, j = r - (r/9)*9;
    int yr = y + i - 4, xr = x + j - 4;
    float m1 = g_m1[b*HW + y*W + x];
    float vin = m1;   // hw-OOB: m2s = 1 -> m1
    if (yr >= 0 && yr < H && xr >= 0 && xr < W)
        vin = m1 * g_m2[b*HW + yr*W + xr];
    float vedge = m1; // d-OOB: m2s = 1 -> m1
    float vals[8];
    #pragma unroll
    for (int z = 0; z < 8; z++) {
        int zz = z + k - 1;
        vals[z] = (zz >= 0 && zz < 8) ? vin : vedge;
    }
    float4* o = (float4*)(om + n * (long)DD);
    o[0] = make_float4(vals[0], vals[1], vals[2], vals[3]);
    o[1] = make_float4(vals[4], vals[5], vals[6], vals[7]);
}

// ---------------------------------------------------------------------------
// Kernel 3: cost volume.
// Block: (b, y, 32-wide x tile). Threads 192: z(8) x txg(8, 4 px each) x k(3).
// f1 tile resident in smem (all 64 c), f2 single-row buffer refilled per
// (i, 16-channel chunk). Per channel: 4 f1 LDS + 12 f2 LDS -> 36 FMAs into
// register accumulators acc[4 px][9 j-shifts]. All LDS bank-conflict-free
// (z-stride padded to 10 -> lane bank = 8*txg + z).
// ---------------------------------------------------------------------------
__global__ void __launch_bounds__(192, 2)
cost_kernel(const float* __restrict__ f1g, const float* __restrict__ f2g,
            float* __restrict__ out) {
    extern __shared__ float sm[];
    float* f1s = sm;             // [64][32][10]
    float* f2s = sm + SMEM_F1;   // [16][40][10]

    const int tid = threadIdx.x;
    const int z   = tid & 7;
    const int txg = (tid >> 3) & 7;
    const int k   = tid >> 6;                 // 0..2
    const int lx0 = txg * 4;
    const int xb  = blockIdx.x * 32;
    const int y   = blockIdx.y;
    const int b   = blockIdx.z;

    // ---- load f1 tile: 64c x 32x x 8z, coalesced over (lx,z) per channel
    {
        const float* src = f1g + (size_t)b * CHWD + (size_t)y * (W*DD) + (size_t)xb * DD;
        for (int n = tid; n < C*32*8; n += 192) {
            int c  = n >> 8;
            int r  = n & 255;
            int lx = r >> 3;
            int zz = r & 7;
            f1s[(c*32 + lx)*10 + zz] = src[(size_t)c * HWD + lx*DD + zz];
        }
    }
    // visibility of f1s is guaranteed by the syncthreads inside the first
    // (i, cc) iteration below.

    float acc[4][9];

    for (int i = 0; i < NS; i++) {
        const int yr = y + i - 4;
        long obase = ((long)(b*NIDX + k*81 + i*9) * HW + (long)y*W + xb + lx0) * DD + z;

        if (yr < 0 || yr >= H) {
            // entire f2 row is zero-padding -> cost = 0 for all 27 (j,k) here
            #pragma unroll
            for (int j = 0; j < 9; j++)
                #pragma unroll
                for (int xi = 0; xi < 4; xi++)
                    out[obase + (long)j*HWD + xi*DD] = 0.f;
            continue;   // uniform branch (depends only on blockIdx.y, i)
        }

        #pragma unroll
        for (int j = 0; j < 9; j++)
            #pragma unroll
            for (int xi = 0; xi < 4; xi++)
                acc[xi][j] = 0.f;

        for (int cc = 0; cc < 4; cc++) {
            __syncthreads();    // previous consumers of f2s done
            // ---- fill f2 row buffer: channels [16cc,16cc+16), row yr,
            //      cols xb-4..xb+35, z padded to [0,10) with zeros at 0 and 9
            {
                const float* src2 = f2g + (size_t)b * CHWD
                                  + (size_t)(cc*16) * HWD + (size_t)yr * (W*DD);
                for (int n = tid; n < SMEM_F2; n += 192) {
                    int cl  = n / 400;
                    int r   = n - cl*400;
                    int col = r / 10;
                    int zi  = r - col*10;
                    float v = 0.f;
                    int gx = xb - 4 + col;
                    if (zi >= 1 && zi <= 8 && gx >= 0 && gx < W)
                        v = src2[(size_t)cl * HWD + gx*DD + (zi - 1)];
                    f2s[n] = v;
                }
            }
            __syncthreads();

            #pragma unroll
            for (int cl = 0; cl < 16; cl++) {
                const float* p1 = &f1s[((cc*16 + cl)*32 + lx0)*10 + z];
                float v0 = p1[0], v1 = p1[10], v2 = p1[20], v3 = p1[30];
                const float* p2 = &f2s[(cl*40 + lx0)*10 + z + k];
                float t[12];
                #pragma unroll
                for (int tt = 0; tt < 12; tt++) t[tt] = p2[tt*10];
                #pragma unroll
                for (int j = 0; j < 9; j++) {
                    acc[0][j] = fmaf(v0, t[j],     acc[0][j]);
                    acc[1][j] = fmaf(v1, t[j + 1], acc[1][j]);
                    acc[2][j] = fmaf(v2, t[j + 2], acc[2][j]);
                    acc[3][j] = fmaf(v3, t[j + 3], acc[3][j]);
                }
            }
        }

        const float sc = 1.0f / 64.0f;   // mean over channels
        #pragma unroll
        for (int j = 0; j < 9; j++)
            #pragma unroll
            for (int xi = 0; xi < 4; xi++)
                out[obase + (long)j*HWD + xi*DD] = acc[xi][j] * sc;
    }
}

// ---------------------------------------------------------------------------
extern "C" void kernel_launch(void* const* d_in, const int* in_sizes, int n_in,
                              void* d_out, int out_size) {
    const float* f1 = (const float*)d_in[0];  // mpi1_features
    const float* a1 = (const float*)d_in[1];  // mpi1_alpha
    const float* f2 = (const float*)d_in[2];  // mpi2_features
    const float* a2 = (const float*)d_in[3];  // mpi2_alpha
    float* out      = (float*)d_out;
    float* out_mask = out + (long)B * NIDX * HWD;

    cudaFuncSetAttribute(cost_kernel,
                         cudaFuncAttributeMaxDynamicSharedMemorySize, SMEM_BYTES);

    mask_sum_kernel<<<(B*HW + 255) / 256, 256>>>(a1, a2);

    long nmask = (long)B * NIDX * HW;
    mask_out_kernel<<<(unsigned)((nmask + 255) / 256), 256>>>(out_mask);

    dim3 g(W / 32, H, B);
    cost_kernel<<<g, 192, SMEM_BYTES>>>(f1, f2, out);
}

// round 2
// speedup vs baseline: 1.7974x; 1.7974x over previous
#include <cuda_runtime.h>

typedef unsigned long long ull;

#define B_   4
#define C_   64
#define H_   96
#define W_   96
#define DD   8
#define HW   (H_*W_)          // 9216
#define HWD  (H_*W_*DD)       // 73728
#define NIDX 243

#define PX   32      // pixels per block along x
#define PT   8       // pixels per thread
#define CCH  8       // channels per stage
#define NST  72      // 9 i-shifts * 8 channel chunks
#define F1COL 34     // 32 cols + pad (stride ≡ 2 mod 4 for conflict-free LDS.64)
#define F2COL 42     // 40 halo cols + pad (≡ 2 mod 4)
#define F1W  (CCH*8*F1COL)     // 2176 words
#define F2W  (CCH*10*F2COL)    // 3360 words
#define SMEM_WORDS (2*F1W + 2*F2W)
#define SMEM_BYTES (SMEM_WORDS*4)

__device__ float g_m1[B_*HW];
__device__ float g_m2[B_*HW];

// ---------------------------------------------------------------------------
// f32x2 helpers (Blackwell packed FMA — PTX-only)
// ---------------------------------------------------------------------------
__device__ __forceinline__ void fma2(ull &d, ull a, ull b) {
    asm("fma.rn.f32x2 %0, %1, %2, %0;" : "+l"(d) : "l"(a), "l"(b));
}
__device__ __forceinline__ ull pack2(float lo, float hi) {
    ull r; asm("mov.b64 %0, {%1, %2};" : "=l"(r) : "f"(lo), "f"(hi)); return r;
}
__device__ __forceinline__ void unpack2(ull v, float &lo, float &hi) {
    asm("mov.b64 {%0, %1}, %2;" : "=f"(lo), "=f"(hi) : "l"(v));
}

// ---------------------------------------------------------------------------
// Stage fill: f1 chunk (8c x 32px x 8z) + f2 halo chunk (8c x 42col x 8z),
// both transposed to col-contiguous layouts. float4 LDG, scalar STS.
// ---------------------------------------------------------------------------
__device__ __forceinline__ void fill_stage(
    float* __restrict__ f1d, float* __restrict__ f2d,
    const float* __restrict__ f1g, const float* __restrict__ f2g,
    int b, int y, int xb, int i, int cc, int tid)
{
    const int cbase = cc * CCH;
    // ---- f1: 512 float4 groups? 8c*32col*2q = 512 elements of float4
    {
        const float* s0 = f1g + (((size_t)(b*C_ + cbase)*H_ + y)*W_ + xb) * DD;
        #pragma unroll
        for (int it = 0; it < 6; it++) {
            int idx = tid + it*96;
            if (idx < 512) {
                int c   = idx >> 6;
                int r   = idx & 63;
                int col = r >> 1;
                int q   = r & 1;
                float4 v = *(const float4*)(s0 + (size_t)c*HWD + col*DD + q*4);
                int wb = (c*8 + q*4)*F1COL + col;
                f1d[wb]          = v.x;
                f1d[wb+F1COL]    = v.y;
                f1d[wb+2*F1COL]  = v.z;
                f1d[wb+3*F1COL]  = v.w;
            }
        }
    }
    // ---- f2: 8cl * 42col * 2q = 672 elements (7 iters exactly)
    {
        const int yr = y + i - 4;
        const bool vrow = (yr >= 0) && (yr < H_);
        const float* s0 = f2g + (((size_t)(b*C_ + cbase)*H_ + (vrow ? yr : 0))) * (size_t)(W_*DD);
        #pragma unroll
        for (int it = 0; it < 7; it++) {
            int idx = tid + it*96;
            int cl  = idx / 84;
            int r   = idx - cl*84;
            int col = r >> 1;
            int q   = r & 1;
            int gx  = xb - 4 + col;
            float4 v = make_float4(0.f, 0.f, 0.f, 0.f);
            if (vrow && gx >= 0 && gx < W_)
                v = *(const float4*)(s0 + (size_t)cl*HWD + gx*DD + q*4);
            int wb = (cl*10 + 1 + q*4)*F2COL + col;
            f2d[wb]          = v.x;
            f2d[wb+F2COL]    = v.y;
            f2d[wb+2*F2COL]  = v.z;
            f2d[wb+3*F2COL]  = v.w;
        }
    }
}

// ---------------------------------------------------------------------------
// Cost kernel. Block = (32-px x-tile, y, b). 96 threads: txg(4, 8px each) x
// z(8) x k(3). Lane map txg=tid&3, z=(tid>>2)&7 makes all LDS.64 2-phase
// conflict-free. Per channel per thread: 4+8 LDS.64, 32 fma.f32x2 + 8 FFMA
// (72 MACs). Double-buffered fills hide L2 latency; one sync per stage.
// ---------------------------------------------------------------------------
__global__ void __launch_bounds__(96, 4)
cost_kernel(const float* __restrict__ f1g, const float* __restrict__ f2g,
            float* __restrict__ out)
{
    extern __shared__ float sm[];
    float* f1b0 = sm;
    float* f1b1 = sm + F1W;
    float* f2b0 = sm + 2*F1W;
    float* f2b1 = sm + 2*F1W + F2W;

    const int tid = threadIdx.x;
    const int txg = tid & 3;
    const int z   = (tid >> 2) & 7;
    const int k   = tid >> 5;            // warp id == k
    const int lx0 = txg * PT;
    const int xb  = blockIdx.x * PX;
    const int y   = blockIdx.y;
    const int b   = blockIdx.z;
    const int zi  = z + k;               // padded f2 z index, 0..9

    // zero the zi=0 / zi=9 pad planes of both f2 buffers (written once)
    for (int n = tid; n < 2*CCH*2*F2COL; n += 96) {
        int p   = n / (CCH*2*F2COL);
        int r   = n - p*(CCH*2*F2COL);
        int cl  = r / (2*F2COL);
        int r2  = r - cl*(2*F2COL);
        int zp  = (r2 >= F2COL) ? 9 : 0;
        int col = (r2 >= F2COL) ? (r2 - F2COL) : r2;
        float* f2p = p ? f2b1 : f2b0;
        f2p[(cl*10 + zp)*F2COL + col] = 0.f;
    }

    ull   acc2[PT][4];
    float accs[PT];

    fill_stage(f1b0, f2b0, f1g, f2g, b, y, xb, 0, 0, tid);

    for (int s = 0; s < NST; s++) {
        const int par = s & 1;
        __syncthreads();   // fill of buf[par] complete; prior compute on buf[par^1] done

        if (s + 1 < NST) {
            fill_stage(par ? f1b0 : f1b1, par ? f2b0 : f2b1,
                       f1g, f2g, b, y, xb, (s+1) >> 3, (s+1) & 7, tid);
        }

        const int i  = s >> 3;
        const int cc = s & 7;

        if (cc == 0) {
            #pragma unroll
            for (int xi = 0; xi < PT; xi++) {
                #pragma unroll
                for (int jp = 0; jp < 4; jp++) acc2[xi][jp] = 0ull;
                accs[xi] = 0.f;
            }
        }

        const float* f1s = par ? f1b1 : f1b0;
        const float* f2s = par ? f2b1 : f2b0;

        #pragma unroll 2
        for (int cl = 0; cl < CCH; cl++) {
            const float* p1 = f1s + (cl*8 + z)*F1COL + lx0;
            float v[8];
            {
                ull a0 = *(const ull*)(p1 + 0);
                ull a1 = *(const ull*)(p1 + 2);
                ull a2 = *(const ull*)(p1 + 4);
                ull a3 = *(const ull*)(p1 + 6);
                unpack2(a0, v[0], v[1]); unpack2(a1, v[2], v[3]);
                unpack2(a2, v[4], v[5]); unpack2(a3, v[6], v[7]);
            }
            const float* p2 = f2s + (cl*10 + zi)*F2COL + lx0;
            ull e[8]; float t[16];
            #pragma unroll
            for (int m = 0; m < 8; m++) {
                e[m] = *(const ull*)(p2 + 2*m);
                unpack2(e[m], t[2*m], t[2*m+1]);
            }
            ull o[7];
            #pragma unroll
            for (int m = 0; m < 7; m++) o[m] = pack2(t[2*m+1], t[2*m+2]);

            #pragma unroll
            for (int xi = 0; xi < PT; xi++) {
                ull vv = pack2(v[xi], v[xi]);
                #pragma unroll
                for (int jp = 0; jp < 4; jp++) {
                    int st = xi + 2*jp;            // start tt of the (j,j+1) pair
                    ull tp = (st & 1) ? o[st >> 1] : e[st >> 1];
                    fma2(acc2[xi][jp], vv, tp);
                }
                accs[xi] = fmaf(v[xi], t[xi + 8], accs[xi]);  // j = 8
            }
        }

        if (cc == 7) {
            const float sc = 1.0f / 64.0f;
            float* ob = out + (((size_t)(b*NIDX + k*81 + i*9))*HW
                               + (size_t)y*W_ + xb + lx0)*DD + z;
            #pragma unroll
            for (int xi = 0; xi < PT; xi++) {
                #pragma unroll
                for (int jp = 0; jp < 4; jp++) {
                    float s0, s1; unpack2(acc2[xi][jp], s0, s1);
                    ob[(size_t)(2*jp)  *HWD + xi*DD] = s0 * sc;
                    ob[(size_t)(2*jp+1)*HWD + xi*DD] = s1 * sc;
                }
                ob[(size_t)8*HWD + xi*DD] = accs[xi] * sc;
            }
        }
    }
}

// ---------------------------------------------------------------------------
// Kernel: per-pixel clipped alpha sums
// ---------------------------------------------------------------------------
__global__ void mask_sum_kernel(const float* __restrict__ a1,
                                const float* __restrict__ a2) {
    int n = blockIdx.x * blockDim.x + threadIdx.x;
    if (n >= B_*HW) return;
    const float4* p1 = (const float4*)(a1 + (size_t)n * DD);
    const float4* p2 = (const float4*)(a2 + (size_t)n * DD);
    float4 u = p1[0], v = p1[1];
    float s1 = u.x+u.y+u.z+u.w + v.x+v.y+v.z+v.w;
    u = p2[0]; v = p2[1];
    float s2 = u.x+u.y+u.z+u.w + v.x+v.y+v.z+v.w;
    g_m1[n] = fminf(fmaxf(s1, 0.f), 1.f);
    g_m2[n] = fminf(fmaxf(s2, 0.f), 1.f);
}

// ---------------------------------------------------------------------------
// Kernel: cost_volume_mask (pure bandwidth). m2 padded with 1.0 everywhere.
// ---------------------------------------------------------------------------
__global__ void mask_out_kernel(float* __restrict__ om) {
    long n = (long)blockIdx.x * blockDim.x + threadIdx.x;
    if (n >= (long)B_*NIDX*HW) return;
    int x   = (int)(n % W_);
    int y   = (int)((n / W_) % H_);
    int idx = (int)((n / HW) % NIDX);
    int b   = (int)(n / ((long)HW * NIDX));
    int kk = idx / 81;
    int r  = idx - kk*81;
    int i  = r / 9, j = r - (r/9)*9;
    int yr = y + i - 4, xr = x + j - 4;
    float m1 = g_m1[b*HW + y*W_ + x];
    float vin = m1;
    if (yr >= 0 && yr < H_ && xr >= 0 && xr < W_)
        vin = m1 * g_m2[b*HW + yr*W_ + xr];
    float vedge = m1;
    float vals[8];
    #pragma unroll
    for (int zz = 0; zz < 8; zz++) {
        int z2 = zz + kk - 1;
        vals[zz] = (z2 >= 0 && z2 < 8) ? vin : vedge;
    }
    float4* o = (float4*)(om + n * (long)DD);
    o[0] = make_float4(vals[0], vals[1], vals[2], vals[3]);
    o[1] = make_float4(vals[4], vals[5], vals[6], vals[7]);
}

// ---------------------------------------------------------------------------
extern "C" void kernel_launch(void* const* d_in, const int* in_sizes, int n_in,
                              void* d_out, int out_size) {
    const float* f1 = (const float*)d_in[0];  // mpi1_features
    const float* a1 = (const float*)d_in[1];  // mpi1_alpha
    const float* f2 = (const float*)d_in[2];  // mpi2_features
    const float* a2 = (const float*)d_in[3];  // mpi2_alpha
    float* out      = (float*)d_out;
    float* out_mask = out + (long)B_ * NIDX * HWD;

    // cost kernel first (independent of mask kernels) — also makes it the
    // launch ncu's skip-window lands on.
    dim3 g(W_ / PX, H_, B_);
    cost_kernel<<<g, 96, SMEM_BYTES>>>(f1, f2, out);

    mask_sum_kernel<<<(B_*HW + 255) / 256, 256>>>(a1, a2);

    long nmask = (long)B_ * NIDX * HW;
    mask_out_kernel<<<(unsigned)((nmask + 255) / 256), 256>>>(out_mask);
}

// round 3
// speedup vs baseline: 1.8132x; 1.0088x over previous
#include <cuda_runtime.h>

typedef unsigned long long ull;

#define B_   4
#define C_   64
#define H_   96
#define W_   96
#define DD   8
#define HW   (H_*W_)          // 9216
#define HWD  (H_*W_*DD)       // 73728
#define NIDX 243
#define CHWD ((size_t)C_*HWD)

#define PX   32      // pixels per block along x
#define PT   8       // pixels per thread
#define CCH  8       // channels per stage
#define NST  72      // 9 i-shifts * 8 channel chunks
#define F1COL 36     // 32 cols + pad; /4 odd -> perfect 4-phase LDS.128
#define F2COL 44     // 40 halo cols + pad; /4 odd -> perfect 4-phase LDS.128
#define F1W  (CCH*8*F1COL)     // 2304 words
#define F2W  (CCH*10*F2COL)    // 3520 words
#define SMEM_WORDS (2*F1W + 2*F2W)
#define SMEM_BYTES (SMEM_WORDS*4)   // 46592 B -> 4 blocks/SM

__device__ float g_m1[B_*HW];
__device__ float g_m2[B_*HW];

// ---------------------------------------------------------------------------
// f32x2 helpers (Blackwell packed math — PTX-only)
// ---------------------------------------------------------------------------
__device__ __forceinline__ void fma2(ull &d, ull a, ull b) {
    asm("fma.rn.f32x2 %0, %1, %2, %0;" : "+l"(d) : "l"(a), "l"(b));
}
__device__ __forceinline__ ull mul2(ull a, ull b) {
    ull d; asm("mul.rn.f32x2 %0, %1, %2;" : "=l"(d) : "l"(a), "l"(b)); return d;
}
__device__ __forceinline__ ull pack2(float lo, float hi) {
    ull r; asm("mov.b64 %0, {%1, %2};" : "=l"(r) : "f"(lo), "f"(hi)); return r;
}
__device__ __forceinline__ void unpack2(ull v, float &lo, float &hi) {
    asm("mov.b64 {%0, %1}, %2;" : "=f"(lo), "=f"(hi) : "l"(v));
}

// ---------------------------------------------------------------------------
// Stage fill: f1 chunk (8c x 32px x 8z) + f2 halo chunk (8c x 42col x 8z),
// transposed to col-contiguous layouts. float4 LDG, scalar STS (conflict-free).
// ---------------------------------------------------------------------------
__device__ __forceinline__ void fill_stage(
    float* __restrict__ f1d, float* __restrict__ f2d,
    const float* __restrict__ f1g, const float* __restrict__ f2g,
    int b, int y, int xb, int i, int cc, int tid, int fcl, int fu)
{
    const int cbase = cc * CCH;
    // ---- f1: 8c * 32col * 2q float4 slots = 512
    {
        const float* s0 = f1g + (((size_t)(b*C_ + cbase)*H_ + y)*W_ + xb) * DD;
        #pragma unroll
        for (int it = 0; it < 6; it++) {
            int idx = tid + it*96;
            if (idx < 512) {
                int c   = idx >> 6;
                int r   = idx & 63;
                int col = r >> 1;
                int q   = r & 1;
                float4 v = *(const float4*)(s0 + (size_t)c*HWD + col*DD + q*4);
                int wb = (c*8 + q*4)*F1COL + col;
                f1d[wb]          = v.x;
                f1d[wb+F1COL]    = v.y;
                f1d[wb+2*F1COL]  = v.z;
                f1d[wb+3*F1COL]  = v.w;
            }
        }
    }
    // ---- f2: per thread fixed channel fcl, slots s = fu + 12*it (84 per ch)
    {
        const int yr = y + i - 4;
        const bool vrow = (yr >= 0) && (yr < H_);
        const float* s0 = f2g + ((size_t)(b*C_ + cbase + fcl)*H_ + (vrow ? yr : 0)) * (size_t)(W_*DD);
        #pragma unroll
        for (int it = 0; it < 7; it++) {
            int s   = fu + it*12;
            int col = s >> 1;
            int q   = s & 1;
            int gx  = xb - 4 + col;
            float4 v = make_float4(0.f, 0.f, 0.f, 0.f);
            if (vrow && gx >= 0 && gx < W_)
                v = *(const float4*)(s0 + gx*DD + q*4);
            int wb = (fcl*10 + 1 + q*4)*F2COL + col;
            f2d[wb]          = v.x;
            f2d[wb+F2COL]    = v.y;
            f2d[wb+2*F2COL]  = v.z;
            f2d[wb+3*F2COL]  = v.w;
        }
    }
}

// ---------------------------------------------------------------------------
// Cost + fused mask kernel. Block = (32-px x-tile, y, b). 96 threads:
// txg(4, 8px) x z(8) x k(3). Per channel per thread: 6 LDS.128 (perfect
// 4-phase) feed 36 fma.f32x2 (72 MACs) — v-pairs and even-j t-pairs are free
// register pairs; 7 odd-shift packs. Double-buffered fills; coalesced 32B
// stores. Mask output fused at end of each i (DRAM was idle).
// ---------------------------------------------------------------------------
__global__ void __launch_bounds__(96, 4)
cost_kernel(const float* __restrict__ f1g, const float* __restrict__ f2g,
            float* __restrict__ out, float* __restrict__ omask)
{
    extern __shared__ float sm[];
    float* f1b0 = sm;
    float* f1b1 = sm + F1W;
    float* f2b0 = sm + 2*F1W;
    float* f2b1 = sm + 2*F1W + F2W;

    const int tid = threadIdx.x;
    const int txg = tid & 3;
    const int z   = (tid >> 2) & 7;
    const int k   = tid >> 5;            // warp id == k
    const int lx0 = txg * PT;
    const int xb  = blockIdx.x * PX;
    const int y   = blockIdx.y;
    const int b   = blockIdx.z;
    const int zi  = z + k;               // padded f2 z index, 0..9
    const int fcl = tid / 12;            // f2-fill channel (0..7)
    const int fu  = tid - fcl*12;

    // zero the zi=0 / zi=9 pad planes of both f2 buffers (written once)
    for (int n = tid; n < 2*CCH*2*F2COL; n += 96) {
        int p   = n / (CCH*2*F2COL);
        int r   = n - p*(CCH*2*F2COL);
        int cl  = r / (2*F2COL);
        int r2  = r - cl*(2*F2COL);
        int zp  = (r2 >= F2COL) ? 9 : 0;
        int col = (r2 >= F2COL) ? (r2 - F2COL) : r2;
        float* f2p = p ? f2b1 : f2b0;
        f2p[(cl*10 + zp)*F2COL + col] = 0.f;
    }

    // mask: per-pixel m1 values for this thread's 8 px (constant per block)
    float m1x[PT];
    {
        const float* m1p = g_m1 + b*HW + y*W_ + xb + lx0;
        float4 a = *(const float4*)(m1p);
        float4 c = *(const float4*)(m1p + 4);
        m1x[0]=a.x; m1x[1]=a.y; m1x[2]=a.z; m1x[3]=a.w;
        m1x[4]=c.x; m1x[5]=c.y; m1x[6]=c.z; m1x[7]=c.w;
    }
    const bool zedge = (zi == 0) || (zi == 9);   // depth-pad rows (m2s = 1)

    ull acc[4][9];

    fill_stage(f1b0, f2b0, f1g, f2g, b, y, xb, 0, 0, tid, fcl, fu);

    for (int s = 0; s < NST; s++) {
        const int par = s & 1;
        __syncthreads();   // fill of buf[par] done; prior compute on buf[par^1] done

        if (s + 1 < NST) {
            fill_stage(par ? f1b0 : f1b1, par ? f2b0 : f2b1,
                       f1g, f2g, b, y, xb, (s+1) >> 3, (s+1) & 7, tid, fcl, fu);
        }

        const int i  = s >> 3;
        const int cc = s & 7;

        if (cc == 0) {
            #pragma unroll
            for (int xp = 0; xp < 4; xp++)
                #pragma unroll
                for (int j = 0; j < 9; j++) acc[xp][j] = 0ull;
        }

        const float* f1s = par ? f1b1 : f1b0;
        const float* f2s = par ? f2b1 : f2b0;

        #pragma unroll 4
        for (int cl = 0; cl < CCH; cl++) {
            const float4* p1 = (const float4*)(f1s + (cl*8 + z)*F1COL + lx0);
            float4 va = p1[0], vb = p1[1];
            ull vp[4];
            vp[0] = pack2(va.x, va.y); vp[1] = pack2(va.z, va.w);
            vp[2] = pack2(vb.x, vb.y); vp[3] = pack2(vb.z, vb.w);

            const float4* p2 = (const float4*)(f2s + (cl*10 + zi)*F2COL + lx0);
            float4 t0 = p2[0], t1 = p2[1], t2 = p2[2], t3 = p2[3];
            ull e[8], o[7];
            e[0] = pack2(t0.x, t0.y); e[1] = pack2(t0.z, t0.w);
            e[2] = pack2(t1.x, t1.y); e[3] = pack2(t1.z, t1.w);
            e[4] = pack2(t2.x, t2.y); e[5] = pack2(t2.z, t2.w);
            e[6] = pack2(t3.x, t3.y); e[7] = pack2(t3.z, t3.w);
            o[0] = pack2(t0.y, t0.z); o[1] = pack2(t0.w, t1.x);
            o[2] = pack2(t1.y, t1.z); o[3] = pack2(t1.w, t2.x);
            o[4] = pack2(t2.y, t2.z); o[5] = pack2(t2.w, t3.x);
            o[6] = pack2(t3.y, t3.z);

            #pragma unroll
            for (int xp = 0; xp < 4; xp++) {
                #pragma unroll
                for (int j = 0; j < 9; j++) {
                    ull tp = (j & 1) ? o[xp + ((j-1)>>1)] : e[xp + (j>>1)];
                    fma2(acc[xp][j], vp[xp], tp);
                }
            }
        }

        if (cc == 7) {
            const ull scc = pack2(1.0f/64.0f, 1.0f/64.0f);
            long obase = ((long)(b*NIDX + k*81 + i*9) * HW
                          + (long)y*W_ + xb + lx0) * DD + z;
            #pragma unroll
            for (int xp = 0; xp < 4; xp++) {
                #pragma unroll
                for (int j = 0; j < 9; j++) {
                    float s0f, s1f; unpack2(mul2(acc[xp][j], scc), s0f, s1f);
                    out[obase + (long)j*HWD + (2*xp  )*DD] = s0f;
                    out[obase + (long)j*HWD + (2*xp+1)*DD] = s1f;
                }
            }
            // ---- fused mask output for this (i, k, z, px-tile)
            const int yr = y + i - 4;
            const bool vrow = (yr >= 0) && (yr < H_);
            float m2w[16];
            #pragma unroll
            for (int n = 0; n < 16; n++) {
                int gxr = xb + lx0 - 4 + n;
                m2w[n] = (vrow && gxr >= 0 && gxr < W_)
                           ? __ldg(g_m2 + b*HW + yr*W_ + gxr) : 1.0f;
            }
            #pragma unroll
            for (int xi = 0; xi < PT; xi++) {
                #pragma unroll
                for (int j = 0; j < 9; j++) {
                    float mv = zedge ? m1x[xi] : (m1x[xi] * m2w[xi + j]);
                    omask[obase + (long)j*HWD + xi*DD] = mv;
                }
            }
        }
    }
}

// ---------------------------------------------------------------------------
// Kernel: per-pixel clipped alpha sums (runs before cost kernel)
// ---------------------------------------------------------------------------
__global__ void mask_sum_kernel(const float* __restrict__ a1,
                                const float* __restrict__ a2) {
    int n = blockIdx.x * blockDim.x + threadIdx.x;
    if (n >= B_*HW) return;
    const float4* p1 = (const float4*)(a1 + (size_t)n * DD);
    const float4* p2 = (const float4*)(a2 + (size_t)n * DD);
    float4 u = p1[0], v = p1[1];
    float s1 = u.x+u.y+u.z+u.w + v.x+v.y+v.z+v.w;
    u = p2[0]; v = p2[1];
    float s2 = u.x+u.y+u.z+u.w + v.x+v.y+v.z+v.w;
    g_m1[n] = fminf(fmaxf(s1, 0.f), 1.f);
    g_m2[n] = fminf(fmaxf(s2, 0.f), 1.f);
}

// ---------------------------------------------------------------------------
extern "C" void kernel_launch(void* const* d_in, const int* in_sizes, int n_in,
                              void* d_out, int out_size) {
    const float* f1 = (const float*)d_in[0];  // mpi1_features
    const float* a1 = (const float*)d_in[1];  // mpi1_alpha
    const float* f2 = (const float*)d_in[2];  // mpi2_features
    const float* a2 = (const float*)d_in[3];  // mpi2_alpha
    float* out      = (float*)d_out;
    float* out_mask = out + (long)B_ * NIDX * HWD;

    mask_sum_kernel<<<(B_*HW + 255) / 256, 256>>>(a1, a2);

    dim3 g(W_ / PX, H_, B_);
    cost_kernel<<<g, 96, SMEM_BYTES>>>(f1, f2, out, out_mask);
}